// round 1
// baseline (speedup 1.0000x reference)
#include <cuda_runtime.h>
#include <cstdint>

#define NN 8192
#define FF 8
#define JT 1024          // j-tile held in shared
#define WARPS 8
#define RPW 7            // rows per warp
#define TPB (WARPS * 32) // 256 threads
#define RPB (WARPS * RPW) // 56 rows per block
#define GRID ((NN + RPB - 1) / RPB) // 147 blocks

typedef unsigned long long ull;

// message-passing output scratch (device global: no allocation allowed)
__device__ float g_mp[NN * FF];

// ---------------- f32x2 helpers (Blackwell packed fp32) ----------------
__device__ __forceinline__ ull fma2(ull a, ull b, ull c) {
    ull d; asm("fma.rn.f32x2 %0, %1, %2, %3;" : "=l"(d) : "l"(a), "l"(b), "l"(c)); return d;
}
__device__ __forceinline__ ull mul2(ull a, ull b) {
    ull d; asm("mul.rn.f32x2 %0, %1, %2;" : "=l"(d) : "l"(a), "l"(b)); return d;
}
__device__ __forceinline__ ull add2(ull a, ull b) {
    ull d; asm("add.rn.f32x2 %0, %1, %2;" : "=l"(d) : "l"(a), "l"(b)); return d;
}
__device__ __forceinline__ ull pack2(float lo, float hi) {
    ull d; asm("mov.b64 %0, {%1, %2};" : "=l"(d) : "f"(lo), "f"(hi)); return d;
}
__device__ __forceinline__ void unpack2(ull v, float& lo, float& hi) {
    asm("mov.b64 {%0, %1}, %2;" : "=f"(lo), "=f"(hi) : "l"(v));
}

// ---------------- main fused kernel: out = max(A, fid) @ X ----------------
// Each warp owns RPW=7 rows. Each lane owns 2 consecutive j per iteration.
// fid test: dot(x_i/s_i, x_j)^2 >= 0.9*s_j^2  (s = ||x||+1e-12), with the
// diagonal intentionally treated as a fid edge (corrected in mlp_kernel).
__global__ void __launch_bounds__(TPB, 1)
mp_kernel(const float* __restrict__ A, const float* __restrict__ X)
{
    __shared__ __align__(16) float2 shx[4][JT]; // feature pair planes: plane kk holds (x[2kk],x[2kk+1]) per j
    __shared__ __align__(16) float  shm[JT];    // m_j = 0.9 * s_j^2

    const int tid  = threadIdx.x;
    const int lane = tid & 31;
    const int warp = tid >> 5;

    int i0 = blockIdx.x * RPB + warp * RPW;
    if (i0 > NN - RPW) i0 = NN - RPW;   // clamp (duplicate rows recompute identical values)

    // ---- per-warp setup: normalized x_i in registers (packed pairs) ----
    ull xin[RPW][4];
    #pragma unroll
    for (int r = 0; r < RPW; r++) {
        const float* xr = X + (size_t)(i0 + r) * FF;
        float v[8];
        float ss = 0.f;
        #pragma unroll
        for (int k = 0; k < 8; k++) { v[k] = __ldg(xr + k); ss += v[k] * v[k]; }
        float s = sqrtf(ss) + 1e-12f;
        float inv = 1.0f / s;
        #pragma unroll
        for (int kk = 0; kk < 4; kk++)
            xin[r][kk] = pack2(v[2 * kk] * inv, v[2 * kk + 1] * inv);
    }

    ull acc[RPW][4];
    #pragma unroll
    for (int r = 0; r < RPW; r++)
        #pragma unroll
        for (int kk = 0; kk < 4; kk++) acc[r][kk] = 0ull; // bits of (0.f,0.f)

    // shared base address (32-bit) for explicit vector LDS
    uint32_t sb;
    asm("{ .reg .u64 t; cvta.to.shared.u64 t, %1; cvt.u32.u64 %0, t; }"
        : "=r"(sb) : "l"(&shx[0][0]));

    for (int t0 = 0; t0 < NN; t0 += JT) {
        __syncthreads(); // previous tile fully consumed
        // ---- cooperative tile fill (x fits in L2; cheap) ----
        for (int j = tid; j < JT; j += TPB) {
            const float4* xp = reinterpret_cast<const float4*>(X + (size_t)(t0 + j) * FF);
            float4 x01 = __ldg(xp);
            float4 x23 = __ldg(xp + 1);
            shx[0][j] = make_float2(x01.x, x01.y);
            shx[1][j] = make_float2(x01.z, x01.w);
            shx[2][j] = make_float2(x23.x, x23.y);
            shx[3][j] = make_float2(x23.z, x23.w);
            float ss = x01.x * x01.x + x01.y * x01.y + x01.z * x01.z + x01.w * x01.w
                     + x23.x * x23.x + x23.y * x23.y + x23.z * x23.z + x23.w * x23.w;
            float s = sqrtf(ss) + 1e-12f;
            shm[j] = 0.9f * s * s;
        }
        __syncthreads();

        const float* Abase = A + (size_t)i0 * NN + t0;

        #pragma unroll 1
        for (int c = 0; c < JT; c += 64) {
            const int jj = c + lane * 2;

            // feature planes for this lane's (j0, j1): one LDS.128 per plane,
            // 16B lane stride -> conflict-free
            ull Pl[4], Ph[4];
            #pragma unroll
            for (int kk = 0; kk < 4; kk++) {
                asm("ld.shared.v2.b64 {%0, %1}, [%2];"
                    : "=l"(Pl[kk]), "=l"(Ph[kk])
                    : "r"(sb + (uint32_t)(kk * (JT * 8) + jj * 8)));
            }
            float2 mm = *reinterpret_cast<const float2*>(&shm[jj]);

            // batch the 7 coalesced A loads (MLP for latency hiding)
            ull av[RPW];
            #pragma unroll
            for (int r = 0; r < RPW; r++)
                av[r] = __ldg(reinterpret_cast<const ull*>(Abase + (size_t)r * NN + jj));

            #pragma unroll
            for (int r = 0; r < RPW; r++) {
                // packed dot over features for j0 and j1
                ull d0 = mul2(xin[r][0], Pl[0]);
                d0 = fma2(xin[r][1], Pl[1], d0);
                d0 = fma2(xin[r][2], Pl[2], d0);
                d0 = fma2(xin[r][3], Pl[3], d0);
                ull d1 = mul2(xin[r][0], Ph[0]);
                d1 = fma2(xin[r][1], Ph[1], d1);
                d1 = fma2(xin[r][2], Ph[2], d1);
                d1 = fma2(xin[r][3], Ph[3], d1);

                float d0l, d0h, d1l, d1h, a0, a1;
                unpack2(d0, d0l, d0h);
                unpack2(d1, d1l, d1h);
                unpack2(av[r], a0, a1);
                float s0 = d0l + d0h;
                float s1 = d1l + d1h;
                float w0 = (s0 * s0 >= mm.x) ? 1.0f : a0;
                float w1 = (s1 * s1 >= mm.y) ? 1.0f : a1;
                ull w02 = pack2(w0, w0);
                ull w12 = pack2(w1, w1);
                #pragma unroll
                for (int kk = 0; kk < 4; kk++)
                    acc[r][kk] = fma2(w02, Pl[kk], acc[r][kk]);
                #pragma unroll
                for (int kk = 0; kk < 4; kk++)
                    acc[r][kk] = fma2(w12, Ph[kk], acc[r][kk]);
            }
        }
    }

    // ---- warp reduction (butterfly over 32 lanes) ----
    #pragma unroll
    for (int r = 0; r < RPW; r++)
        #pragma unroll
        for (int kk = 0; kk < 4; kk++) {
            ull v = acc[r][kk];
            #pragma unroll
            for (int o = 16; o; o >>= 1)
                v = add2(v, __shfl_xor_sync(0xffffffffu, v, o));
            acc[r][kk] = v;
        }

    if (lane < RPW) {
        int row = i0 + lane;
        float2* out = reinterpret_cast<float2*>(&g_mp[(size_t)row * FF]);
        #pragma unroll
        for (int kk = 0; kk < 4; kk++) {
            float lo, hi;
            unpack2(acc[lane][kk], lo, hi);
            out[kk] = make_float2(lo, hi);
        }
    }
}

// ---------------- tiny MLP tail (per-row) ----------------
template <int IN, int OUT>
__device__ __forceinline__ void layer_tanh(const float* in, float* out,
                                           const float* __restrict__ W,
                                           const float* __restrict__ b)
{
    #pragma unroll
    for (int j = 0; j < OUT; j++) {
        float s = __ldg(b + j);
        #pragma unroll
        for (int k = 0; k < IN; k++)
            s = fmaf(in[k], __ldg(W + k * OUT + j), s);
        out[j] = tanhf(s);
    }
}

__global__ void mlp_kernel(const float* __restrict__ A, const float* __restrict__ X,
                           const float* __restrict__ Wfm, const float* __restrict__ bfm,
                           const float* __restrict__ Wc1, const float* __restrict__ bc1,
                           const float* __restrict__ Wp1, const float* __restrict__ bp1,
                           const float* __restrict__ Wc2, const float* __restrict__ bc2,
                           const float* __restrict__ Wp2, const float* __restrict__ bp2,
                           const float* __restrict__ Wc3, const float* __restrict__ bc3,
                           const float* __restrict__ Wh,  const float* __restrict__ bh,
                           float* __restrict__ out)
{
    int i = blockIdx.x * blockDim.x + threadIdx.x;
    if (i >= NN) return;

    // diagonal correction: inner loop treated j==i as fid edge (w=1); the
    // reference excludes self-edges, so real weight is A_ii.
    float aii = __ldg(A + (size_t)i * NN + i);
    float v[8];
    #pragma unroll
    for (int k = 0; k < 8; k++)
        v[k] = g_mp[(size_t)i * FF + k] + (aii - 1.0f) * __ldg(X + (size_t)i * FF + k);

    float h1[16], h2[16], h3[12], h4[8], h5[4], h6[4];
    layer_tanh<8, 16>(v,  h1, Wfm, bfm);
    layer_tanh<16, 16>(h1, h2, Wc1, bc1);
    layer_tanh<16, 12>(h2, h3, Wp1, bp1);
    layer_tanh<12, 8>(h3, h4, Wc2, bc2);
    layer_tanh<8, 4>(h4, h5, Wp2, bp2);
    layer_tanh<4, 4>(h5, h6, Wc3, bc3);

    float z = __ldg(bh);
    #pragma unroll
    for (int k = 0; k < 4; k++)
        z = fmaf(h6[k], __ldg(Wh + k), z);
    out[i] = 1.0f / (1.0f + expf(-z));
}

extern "C" void kernel_launch(void* const* d_in, const int* in_sizes, int n_in,
                              void* d_out, int out_size)
{
    const float* A = (const float*)d_in[0];
    const float* X = (const float*)d_in[1];

    mp_kernel<<<GRID, TPB>>>(A, X);

    mlp_kernel<<<(NN + 255) / 256, 256>>>(
        A, X,
        (const float*)d_in[2],  (const float*)d_in[3],
        (const float*)d_in[4],  (const float*)d_in[5],
        (const float*)d_in[6],  (const float*)d_in[7],
        (const float*)d_in[8],  (const float*)d_in[9],
        (const float*)d_in[10], (const float*)d_in[11],
        (const float*)d_in[12], (const float*)d_in[13],
        (const float*)d_in[14], (const float*)d_in[15],
        (float*)d_out);
}

// round 2
// speedup vs baseline: 1.5053x; 1.5053x over previous
#include <cuda_runtime.h>
#include <cstdint>

#define NN 8192
#define FF 8
#define JT 1024           // j-tile held in shared
#define WARPS 8
#define RPW 7             // rows per warp
#define TPB (WARPS * 32)  // 256 threads
#define RPB (WARPS * RPW) // 56 rows per block
#define GRID ((NN + RPB - 1) / RPB) // 147 blocks
#define NITER (NN / 64)   // 128 j-chunks of 64
#define IPT (JT / 64)     // 16 chunks per tile

typedef unsigned long long ull;

// ---------------- f32x2 helpers (Blackwell packed fp32) ----------------
__device__ __forceinline__ ull fma2(ull a, ull b, ull c) {
    ull d; asm("fma.rn.f32x2 %0, %1, %2, %3;" : "=l"(d) : "l"(a), "l"(b), "l"(c)); return d;
}
__device__ __forceinline__ ull mul2(ull a, ull b) {
    ull d; asm("mul.rn.f32x2 %0, %1, %2;" : "=l"(d) : "l"(a), "l"(b)); return d;
}
__device__ __forceinline__ ull add2(ull a, ull b) {
    ull d; asm("add.rn.f32x2 %0, %1, %2;" : "=l"(d) : "l"(a), "l"(b)); return d;
}
__device__ __forceinline__ ull pack2(float lo, float hi) {
    ull d; asm("mov.b64 %0, {%1, %2};" : "=l"(d) : "f"(lo), "f"(hi)); return d;
}
__device__ __forceinline__ void unpack2(ull v, float& lo, float& hi) {
    asm("mov.b64 {%0, %1}, %2;" : "=f"(lo), "=f"(hi) : "l"(v));
}

// overflow-safe fast tanh / sigmoid (MUFU-based, ~1e-6 rel err)
__device__ __forceinline__ float ftanh(float x) {
    float t = fabsf(x);
    float e = __expf(-2.0f * t);                 // always in (0,1]
    float r = __fdividef(1.0f - e, 1.0f + e);
    return copysignf(r, x);
}
__device__ __forceinline__ float fsigmoid(float x) {
    float e = __expf(-fabsf(x));
    float p = __fdividef(1.0f, 1.0f + e);
    return (x >= 0.0f) ? p : 1.0f - p;
}

template <int IN, int OUT>
__device__ __forceinline__ void layer_tanh(const float* in, float* out,
                                           const float* __restrict__ W,
                                           const float* __restrict__ b)
{
    #pragma unroll
    for (int j = 0; j < OUT; j++) {
        float s = __ldg(b + j);
        #pragma unroll
        for (int k = 0; k < IN; k++)
            s = fmaf(in[k], __ldg(W + k * OUT + j), s);
        out[j] = ftanh(s);
    }
}

// ---------------- fully fused kernel ----------------
// out_i = sigmoid(head(MLP( max(A, fid) @ X )))
// fid test: |(x_i/s_i) . x_j| >= sqrt(0.9) * s_j   (s = ||x||+1e-12)
// diagonal treated as fid edge in the loop, corrected in the MLP tail.
__global__ void __launch_bounds__(TPB, 1)
fused_kernel(const float* __restrict__ A, const float* __restrict__ X,
             const float* __restrict__ Wfm, const float* __restrict__ bfm,
             const float* __restrict__ Wc1, const float* __restrict__ bc1,
             const float* __restrict__ Wp1, const float* __restrict__ bp1,
             const float* __restrict__ Wc2, const float* __restrict__ bc2,
             const float* __restrict__ Wp2, const float* __restrict__ bp2,
             const float* __restrict__ Wc3, const float* __restrict__ bc3,
             const float* __restrict__ Wh,  const float* __restrict__ bh,
             float* __restrict__ out)
{
    __shared__ __align__(16) float2 shx[4][JT]; // feature-pair planes
    __shared__ __align__(16) float  shm[JT];    // sqrt(0.9) * s_j

    const int tid  = threadIdx.x;
    const int lane = tid & 31;
    const int warp = tid >> 5;

    int i0 = blockIdx.x * RPB + warp * RPW;
    if (i0 > NN - RPW) i0 = NN - RPW; // clamp: duplicate rows write identical values

    // ---- normalized x_i in registers ----
    ull xin[RPW][4];
    #pragma unroll
    for (int r = 0; r < RPW; r++) {
        const float4* xp = reinterpret_cast<const float4*>(X + (size_t)(i0 + r) * FF);
        float4 a = __ldg(xp), b = __ldg(xp + 1);
        float ss = a.x*a.x + a.y*a.y + a.z*a.z + a.w*a.w
                 + b.x*b.x + b.y*b.y + b.z*b.z + b.w*b.w;
        float inv = 1.0f / (sqrtf(ss) + 1e-12f);
        xin[r][0] = pack2(a.x*inv, a.y*inv);
        xin[r][1] = pack2(a.z*inv, a.w*inv);
        xin[r][2] = pack2(b.x*inv, b.y*inv);
        xin[r][3] = pack2(b.z*inv, b.w*inv);
    }

    ull acc[RPW][4];
    #pragma unroll
    for (int r = 0; r < RPW; r++)
        #pragma unroll
        for (int kk = 0; kk < 4; kk++) acc[r][kk] = 0ull;

    uint32_t sb;
    asm("{ .reg .u64 t; cvta.to.shared.u64 t, %1; cvt.u32.u64 %0, t; }"
        : "=r"(sb) : "l"(&shx[0][0]));

    const float* Ab = A + (size_t)i0 * NN + lane * 2;

    // depth-2 A-row prefetch buffers
    ull bufA[RPW], bufB[RPW];

    #define LDA(n, buf)                                                        \
        do {                                                                   \
            const float* p_ = Ab + (size_t)(n) * 64;                           \
            _Pragma("unroll")                                                  \
            for (int r_ = 0; r_ < RPW; r_++)                                   \
                (buf)[r_] = __ldg(reinterpret_cast<const ull*>(p_ + (size_t)r_ * NN)); \
        } while (0)

    #define COMPUTE(jj, buf)                                                   \
        do {                                                                   \
            ull Pl_[4], Ph_[4];                                                \
            _Pragma("unroll")                                                  \
            for (int kk_ = 0; kk_ < 4; kk_++) {                                \
                asm("ld.shared.v2.b64 {%0, %1}, [%2];"                         \
                    : "=l"(Pl_[kk_]), "=l"(Ph_[kk_])                           \
                    : "r"(sb + (uint32_t)(kk_ * (JT * 8) + (jj) * 8)));        \
            }                                                                  \
            float2 mm_ = *reinterpret_cast<const float2*>(&shm[(jj)]);         \
            _Pragma("unroll")                                                  \
            for (int r_ = 0; r_ < RPW; r_++) {                                 \
                ull d0_ = mul2(xin[r_][0], Pl_[0]);                            \
                d0_ = fma2(xin[r_][1], Pl_[1], d0_);                           \
                d0_ = fma2(xin[r_][2], Pl_[2], d0_);                           \
                d0_ = fma2(xin[r_][3], Pl_[3], d0_);                           \
                ull d1_ = mul2(xin[r_][0], Ph_[0]);                            \
                d1_ = fma2(xin[r_][1], Ph_[1], d1_);                           \
                d1_ = fma2(xin[r_][2], Ph_[2], d1_);                           \
                d1_ = fma2(xin[r_][3], Ph_[3], d1_);                           \
                float d0l_, d0h_, d1l_, d1h_, a0_, a1_;                        \
                unpack2(d0_, d0l_, d0h_);                                      \
                unpack2(d1_, d1l_, d1h_);                                      \
                unpack2((buf)[r_], a0_, a1_);                                  \
                float s0_ = d0l_ + d0h_;                                       \
                float s1_ = d1l_ + d1h_;                                       \
                float w0_ = (fabsf(s0_) >= mm_.x) ? 1.0f : a0_;                \
                float w1_ = (fabsf(s1_) >= mm_.y) ? 1.0f : a1_;                \
                ull w02_ = pack2(w0_, w0_);                                    \
                ull w12_ = pack2(w1_, w1_);                                    \
                _Pragma("unroll")                                              \
                for (int kk_ = 0; kk_ < 4; kk_++)                              \
                    acc[r_][kk_] = fma2(w02_, Pl_[kk_], acc[r_][kk_]);         \
                _Pragma("unroll")                                              \
                for (int kk_ = 0; kk_ < 4; kk_++)                              \
                    acc[r_][kk_] = fma2(w12_, Ph_[kk_], acc[r_][kk_]);         \
            }                                                                  \
        } while (0)

    LDA(0, bufA);
    LDA(1, bufB);

    for (int t = 0; t < NN / JT; t++) {
        __syncthreads(); // previous tile fully consumed
        const int t0 = t * JT;
        for (int j = tid; j < JT; j += TPB) {
            const float4* xp = reinterpret_cast<const float4*>(X + (size_t)(t0 + j) * FF);
            float4 a = __ldg(xp), b = __ldg(xp + 1);
            shx[0][j] = make_float2(a.x, a.y);
            shx[1][j] = make_float2(a.z, a.w);
            shx[2][j] = make_float2(b.x, b.y);
            shx[3][j] = make_float2(b.z, b.w);
            float ss = a.x*a.x + a.y*a.y + a.z*a.z + a.w*a.w
                     + b.x*b.x + b.y*b.y + b.z*b.z + b.w*b.w;
            shm[j] = 0.94868329805f * (sqrtf(ss) + 1e-12f); // sqrt(0.9)*s_j
        }
        __syncthreads();

        #pragma unroll 1
        for (int cc = 0; cc < IPT; cc += 2) {
            const int n = t * IPT + cc;
            const int jj = cc * 64 + lane * 2;
            COMPUTE(jj, bufA);
            { int np = n + 2; if (np >= NITER) np = 0; LDA(np, bufA); }
            COMPUTE(jj + 64, bufB);
            { int np = n + 3; if (np >= NITER) np = 0; LDA(np, bufB); }
        }
    }

    // ---- warp butterfly reduction ----
    #pragma unroll
    for (int r = 0; r < RPW; r++)
        #pragma unroll
        for (int kk = 0; kk < 4; kk++) {
            ull v = acc[r][kk];
            #pragma unroll
            for (int o = 16; o; o >>= 1)
                v = add2(v, __shfl_xor_sync(0xffffffffu, v, o));
            acc[r][kk] = v;
        }

    // ---- fused MLP tail: lane r handles row i0+r ----
    if (lane < RPW) {
        const int i = i0 + lane;
        // diagonal correction: loop treated j==i as fid edge (w=1), reference
        // excludes self-edges -> real weight is A_ii.
        float aii = __ldg(A + (size_t)i * NN + i);
        const float4* xp = reinterpret_cast<const float4*>(X + (size_t)i * FF);
        float4 xa = __ldg(xp), xb = __ldg(xp + 1);
        float xi[8] = {xa.x, xa.y, xa.z, xa.w, xb.x, xb.y, xb.z, xb.w};

        float v[8];
        #pragma unroll
        for (int kk = 0; kk < 4; kk++) {
            float lo, hi;
            unpack2(acc[lane][kk], lo, hi);
            v[2*kk]   = lo + (aii - 1.0f) * xi[2*kk];
            v[2*kk+1] = hi + (aii - 1.0f) * xi[2*kk+1];
        }

        float h1[16], h2[16], h3[12], h4[8], h5[4], h6[4];
        layer_tanh<8, 16>(v,  h1, Wfm, bfm);
        layer_tanh<16,16>(h1, h2, Wc1, bc1);
        layer_tanh<16,12>(h2, h3, Wp1, bp1);
        layer_tanh<12, 8>(h3, h4, Wc2, bc2);
        layer_tanh<8,  4>(h4, h5, Wp2, bp2);
        layer_tanh<4,  4>(h5, h6, Wc3, bc3);

        float z = __ldg(bh);
        #pragma unroll
        for (int k = 0; k < 4; k++)
            z = fmaf(h6[k], __ldg(Wh + k), z);
        out[i] = fsigmoid(z);
    }
}

extern "C" void kernel_launch(void* const* d_in, const int* in_sizes, int n_in,
                              void* d_out, int out_size)
{
    fused_kernel<<<GRID, TPB>>>(
        (const float*)d_in[0],  (const float*)d_in[1],
        (const float*)d_in[2],  (const float*)d_in[3],
        (const float*)d_in[4],  (const float*)d_in[5],
        (const float*)d_in[6],  (const float*)d_in[7],
        (const float*)d_in[8],  (const float*)d_in[9],
        (const float*)d_in[10], (const float*)d_in[11],
        (const float*)d_in[12], (const float*)d_in[13],
        (const float*)d_in[14], (const float*)d_in[15],
        (float*)d_out);
}